// round 3
// baseline (speedup 1.0000x reference)
#include <cuda_runtime.h>
#include <math.h>

#define HH 512
#define WW 512
#define BB 2
#define HWSZ (HH*WW)          // 262144
#define NPIX (BB*HWSZ)        // 524288
#define TOPK 2048
#define CAP 262144
#define NKP (BB*TOPK)         // 4096

// output layout: kxy (B,K,2) | desc (B,K,128) | kptscores (B,K) | disp (B,K)
#define KXY_OFF  0
#define DESC_OFF (BB*TOPK*2)                 // 8192
#define SC_OFF   (DESC_OFF + BB*TOPK*128)    // 532480
#define DISP_OFF (SC_OFF + BB*TOPK)          // 536576

__device__ float g_tmp[NPIX];
__device__ float g_mmf[NPIX];
__device__ float g_ss[NPIX];
__device__ float g_smf[NPIX];
__device__ unsigned long long g_cand[BB*CAP];
__device__ int g_count[BB];
__device__ int g_selidx[NKP];

// ---- vertical max within row-half ([0,255] or [256,511]), radius 3 ----
// SRC: 0 = scores (param), 1 = g_mmf, 2 = g_ss.  Writes g_tmp.
template<int SRC>
__global__ void vmax_k(const float* __restrict__ scores) {
    int i = blockIdx.x * blockDim.x + threadIdx.x;
    if (i >= NPIX) return;
    int rem = i & (HWSZ - 1);
    int y = rem >> 9;
    int lo = (y < 256) ? 0 : 256;
    int hi = lo + 255;
    int y0 = max(lo, y - 3), y1 = min(hi, y + 3);
    int col = i - (y << 9);   // b*HWSZ + x
    float m = -INFINITY;
    for (int yy = y0; yy <= y1; ++yy) {
        int j = col + (yy << 9);
        float v = (SRC == 0) ? scores[j] : (SRC == 1) ? g_mmf[j] : g_ss[j];
        m = fmaxf(m, v);
    }
    g_tmp[i] = m;
}

__device__ __forceinline__ float hmax_at(int i) {
    int x = i & 511;
    int rowbase = i - x;
    int x0 = max(0, x - 3), x1 = min(511, x + 3);
    float m = -INFINITY;
    for (int xx = x0; xx <= x1; ++xx) m = fmaxf(m, g_tmp[rowbase + xx]);
    return m;
}

// pool = maxpool(s); mm = (s == pool)
__global__ void hmax_init_k(const float* __restrict__ scores) {
    int i = blockIdx.x * blockDim.x + threadIdx.x;
    if (i >= NPIX) return;
    g_mmf[i] = (scores[i] == hmax_at(i)) ? 1.0f : 0.0f;
}

// pool = maxpool(mm); sm = pool>0; ss = sm ? 0 : s
__global__ void hmax_supp_k(const float* __restrict__ scores) {
    int i = blockIdx.x * blockDim.x + threadIdx.x;
    if (i >= NPIX) return;
    bool sm = hmax_at(i) > 0.0f;
    g_smf[i] = sm ? 1.0f : 0.0f;
    g_ss[i] = sm ? 0.0f : scores[i];
}

// pool = maxpool(ss); mm |= (ss == pool) & ~sm
__global__ void hmax_update_k() {
    int i = blockIdx.x * blockDim.x + threadIdx.x;
    if (i >= NPIX) return;
    if (g_mmf[i] == 0.0f && g_smf[i] == 0.0f && g_ss[i] == hmax_at(i))
        g_mmf[i] = 1.0f;
}

__global__ void reset_k() {
    int i = threadIdx.x;
    if (i < BB) g_count[i] = 0;
}

// nms = (mm && border) ? s : 0 ; push candidates (nms>0 or flatidx<2048)
__global__ void compact_k(const float* __restrict__ scores) {
    int i = blockIdx.x * blockDim.x + threadIdx.x;
    if (i >= NPIX) return;
    int b = i >> 18;
    int rem = i & (HWSZ - 1);
    int y = rem >> 9;
    int x = rem & 511;
    bool border = (y >= 3) && (y < 510) && (x >= 3) && (x < 510);
    float nms = (g_mmf[i] > 0.0f && border) ? scores[i] : 0.0f;
    if (nms > 0.0f || rem < TOPK) {
        int pos = atomicAdd(&g_count[b], 1);
        if (pos < CAP) {
            unsigned long long key =
                ((unsigned long long)__float_as_uint(nms) << 32) |
                (unsigned long long)(0xFFFFFFFFu - (unsigned)rem);
            g_cand[b * CAP + pos] = key;
        }
    }
}

// exact top-k by rank counting: rank = #{keys > mykey}; unique keys -> exact order
__global__ void rank_k() {
    int b = blockIdx.y;
    int cnt = g_count[b];
    if ((int)(blockIdx.x * blockDim.x) >= cnt) return;   // block-uniform early exit
    int i = blockIdx.x * blockDim.x + threadIdx.x;
    const unsigned long long* cand = g_cand + b * CAP;
    unsigned long long mykey = (i < cnt) ? cand[i] : 0ull;
    int rank = 0;
    __shared__ unsigned long long sk[256];
    for (int t = 0; t < cnt; t += 256) {
        int j = t + threadIdx.x;
        sk[threadIdx.x] = (j < cnt) ? cand[j] : 0ull;
        __syncthreads();
        int lim = min(256, cnt - t);
        if (i < cnt) {
            for (int u = 0; u < lim; ++u) rank += (sk[u] > mykey) ? 1 : 0;
        }
        __syncthreads();
    }
    if (i < cnt && rank < TOPK) {
        int flatidx = (int)(0xFFFFFFFFu - (unsigned)(mykey & 0xFFFFFFFFull));
        g_selidx[b * TOPK + rank] = flatidx;
    }
}

__device__ __forceinline__ float bilin1(const float* base, float x, float y) {
    float x0f = floorf(x), y0f = floorf(y);
    float wx = x - x0f, wy = y - y0f;
    int x0 = min(max((int)x0f, 0), WW - 1);
    int x1 = min(max((int)x0f + 1, 0), WW - 1);
    int y0 = min(max((int)y0f, 0), HH - 1);
    int y1 = min(max((int)y0f + 1, 0), HH - 1);
    float v00 = base[y0 * WW + x0], v01 = base[y0 * WW + x1];
    float v10 = base[y1 * WW + x0], v11 = base[y1 * WW + x1];
    return v00 * (1.f - wx) * (1.f - wy) + v01 * wx * (1.f - wy)
         + v10 * (1.f - wx) * wy + v11 * wx * wy;
}

// per-keypoint: 5x5 softmax refinement -> kxy, disp, kptscores
__global__ void refine_k(const float* __restrict__ scores, float* __restrict__ out) {
    int t = blockIdx.x * blockDim.x + threadIdx.x;
    if (t >= NKP) return;
    int b = t >> 11;
    int idx = g_selidx[t];
    int ky = idx >> 9, kx = idx & 511;
    const float* sb = scores + b * HWSZ;

    float patch[25];
    float maxv = -INFINITY;
#pragma unroll
    for (int p = 0; p < 25; ++p) {
        int dy = p / 5 - 2, dx = p % 5 - 2;
        int y = ky + dy, x = kx + dx;
        float v = (y >= 0 && y < HH && x >= 0 && x < WW) ? sb[y * WW + x] : 0.0f;
        patch[p] = v;
        maxv = fmaxf(maxv, v);
    }
    float ex[25];
    float ssum = 0.f, sx = 0.f, sy = 0.f;
#pragma unroll
    for (int p = 0; p < 25; ++p) {
        float e = expf((patch[p] - maxv) / 0.1f);
        ex[p] = e;
        ssum += e;
        sx += e * (float)(p % 5 - 2);
        sy += e * (float)(p / 5 - 2);
    }
    float rx = sx / ssum, ry = sy / ssum;
    float disp = 0.f;
#pragma unroll
    for (int p = 0; p < 25; ++p) {
        float ddx = ((float)(p % 5 - 2) - rx) * 0.5f;
        float ddy = ((float)(p / 5 - 2) - ry) * 0.5f;
        disp += ex[p] * (ddx * ddx + ddy * ddy);
    }
    disp /= ssum;

    float kxf = ((float)kx + rx) / 511.f * 2.f - 1.f;
    float kyf = ((float)ky + ry) / 511.f * 2.f - 1.f;
    out[KXY_OFF + t * 2 + 0] = kxf;
    out[KXY_OFF + t * 2 + 1] = kyf;
    out[DISP_OFF + t] = disp;

    float xs = (kxf + 1.f) * 0.5f * (WW - 1);
    float ys = (kyf + 1.f) * 0.5f * (HH - 1);
    out[SC_OFF + t] = bilin1(sb, xs, ys);
}

// per-keypoint block of 128 threads: bilinear desc + L2 normalize
__global__ void desc_k(const float* __restrict__ dmap, float* __restrict__ out) {
    int t = blockIdx.x;      // keypoint
    int c = threadIdx.x;     // channel
    int b = t >> 11;
    float kxf = out[KXY_OFF + t * 2 + 0];
    float kyf = out[KXY_OFF + t * 2 + 1];
    float x = (kxf + 1.f) * 0.5f * (WW - 1);
    float y = (kyf + 1.f) * 0.5f * (HH - 1);
    float x0f = floorf(x), y0f = floorf(y);
    float wx = x - x0f, wy = y - y0f;
    int x0 = min(max((int)x0f, 0), WW - 1);
    int x1 = min(max((int)x0f + 1, 0), WW - 1);
    int y0 = min(max((int)y0f, 0), HH - 1);
    int y1 = min(max((int)y0f + 1, 0), HH - 1);
    const float* base = dmap + ((size_t)b * 128 + c) * HWSZ;
    float v00 = base[y0 * WW + x0], v01 = base[y0 * WW + x1];
    float v10 = base[y1 * WW + x0], v11 = base[y1 * WW + x1];
    float v = v00 * (1.f - wx) * (1.f - wy) + v01 * wx * (1.f - wy)
            + v10 * (1.f - wx) * wy + v11 * wx * wy;

    __shared__ float red[128];
    red[c] = v * v;
    __syncthreads();
#pragma unroll
    for (int s = 64; s > 0; s >>= 1) {
        if (c < s) red[c] += red[c + s];
        __syncthreads();
    }
    float nrm = fmaxf(sqrtf(red[0]), 1e-12f);
    out[DESC_OFF + (size_t)t * 128 + c] = v / nrm;
}

extern "C" void kernel_launch(void* const* d_in, const int* in_sizes, int n_in,
                              void* d_out, int out_size) {
    // Identify inputs by element count (robust to metadata order):
    // scores_map: 524288 ; descriptor_map: 67108864
    const float* scores;
    const float* dmap;
    if (in_sizes[0] == NPIX) {
        scores = (const float*)d_in[0];
        dmap   = (const float*)d_in[1];
    } else {
        scores = (const float*)d_in[1];
        dmap   = (const float*)d_in[0];
    }
    float* out = (float*)d_out;

    const int TB = 256;
    const int NB = (NPIX + TB - 1) / TB;

    // mm = (s == maxpool(s))
    vmax_k<0><<<NB, TB>>>(scores);
    hmax_init_k<<<NB, TB>>>(scores);

    // two NMS recovery iterations
    for (int it = 0; it < 2; ++it) {
        vmax_k<1><<<NB, TB>>>(scores);     // pool of mm
        hmax_supp_k<<<NB, TB>>>(scores);
        vmax_k<2><<<NB, TB>>>(scores);     // pool of ss
        hmax_update_k<<<NB, TB>>>();
    }

    reset_k<<<1, 32>>>();
    compact_k<<<NB, TB>>>(scores);

    dim3 rgrid(CAP / 256, BB);
    rank_k<<<rgrid, 256>>>();

    refine_k<<<(NKP + 127) / 128, 128>>>(scores, out);
    desc_k<<<NKP, 128>>>(dmap, out);
}

// round 4
// speedup vs baseline: 1.1465x; 1.1465x over previous
#include <cuda_runtime.h>
#include <math.h>

#define HH 512
#define WW 512
#define BB 2
#define HWSZ (HH*WW)          // 262144
#define NPIX (BB*HWSZ)        // 524288
#define TOPK 2048
#define CAP 262144
#define NKP (BB*TOPK)         // 4096

// output layout: kxy (B,K,2) | desc (B,K,128) | kptscores (B,K) | disp (B,K)
#define KXY_OFF  0
#define DESC_OFF (BB*TOPK*2)                 // 8192
#define SC_OFF   (DESC_OFF + BB*TOPK*128)    // 532480
#define DISP_OFF (SC_OFF + BB*TOPK)          // 536576

__device__ float g_mm[NPIX];
__device__ float g_ss[NPIX];
__device__ float g_smf[NPIX];
__device__ unsigned long long g_cand[BB*CAP];
__device__ int g_count[BB];
__device__ int g_selidx[NKP];

#define TX 64
#define TY 16

// fused (vertical+horizontal) 7x7 maxpool with split halves + elementwise op.
// SRC: 0=scores, 1=g_mm, 2=g_ss.  OP: 0=init, 1=supp, 2=update, 3=update+compact
template<int SRC, int OP>
__global__ __launch_bounds__(256) void pool_k(const float* __restrict__ scores) {
    __shared__ float sin_[TY+6][TX+6];
    __shared__ float svm[TY][TX+6];
    int tid = threadIdx.x;
    int b = blockIdx.z;
    int xt = blockIdx.x * TX;
    int yt = blockIdx.y * TY;
    int x0 = xt - 3, y0 = yt - 3;
    int hlo = (yt < 256) ? 0 : 256;
    int hhi = hlo + 255;
    const float* sb = scores + b * HWSZ;

    // load tile + halo (OOB / cross-half -> -inf)
    for (int idx = tid; idx < (TY+6)*(TX+6); idx += 256) {
        int ly = idx / (TX+6), lx = idx % (TX+6);
        int gy = y0 + ly, gx = x0 + lx;
        float v = -INFINITY;
        if (gx >= 0 && gx < WW && gy >= hlo && gy <= hhi) {
            int j = b * HWSZ + gy * WW + gx;
            v = (SRC == 0) ? sb[gy * WW + gx] : (SRC == 1) ? g_mm[j] : g_ss[j];
        }
        sin_[ly][lx] = v;
    }
    __syncthreads();

    // vertical max
    for (int idx = tid; idx < TY*(TX+6); idx += 256) {
        int ly = idx / (TX+6), lx = idx % (TX+6);
        float m = sin_[ly][lx];
#pragma unroll
        for (int d = 1; d < 7; ++d) m = fmaxf(m, sin_[ly+d][lx]);
        svm[ly][lx] = m;
    }
    __syncthreads();

    // horizontal max + op, 4 output rows per thread
    int ox = tid % TX;
    int oyb = tid / TX;     // 0..3
#pragma unroll
    for (int r = 0; r < 4; ++r) {
        int oy = oyb * 4 + r;
        float m = svm[oy][ox];
#pragma unroll
        for (int d = 1; d < 7; ++d) m = fmaxf(m, svm[oy][ox+d]);
        int gy = yt + oy, gx = xt + ox;
        int i = b * HWSZ + gy * WW + gx;
        if (OP == 0) {
            g_mm[i] = (sb[gy * WW + gx] == m) ? 1.0f : 0.0f;
        } else if (OP == 1) {
            bool sm = m > 0.0f;
            g_smf[i] = sm ? 1.0f : 0.0f;
            g_ss[i]  = sm ? 0.0f : sb[gy * WW + gx];
        } else {
            float mm = g_mm[i];
            if (mm == 0.0f && g_smf[i] == 0.0f && g_ss[i] == m) {
                mm = 1.0f;
                if (OP == 2) g_mm[i] = 1.0f;
            }
            if (OP == 3) {
                int rem = gy * WW + gx;
                bool border = (gy >= 3) && (gy < HH-2) && (gx >= 3) && (gx < WW-2);
                float nms = (mm > 0.0f && border) ? sb[gy * WW + gx] : 0.0f;
                if (nms > 0.0f || rem < TOPK) {
                    int pos = atomicAdd(&g_count[b], 1);
                    if (pos < CAP) {
                        unsigned long long key =
                            ((unsigned long long)__float_as_uint(nms) << 32) |
                            (unsigned long long)(0xFFFFFFFFu - (unsigned)rem);
                        g_cand[b * CAP + pos] = key;
                    }
                }
            }
        }
    }
}

__global__ void reset_k() {
    if (threadIdx.x < BB) g_count[threadIdx.x] = 0;
}

// exact top-k by rank counting (keys unique -> exact (val desc, idx asc) order)
__global__ __launch_bounds__(256) void rank_k() {
    int b = blockIdx.y;
    int cnt = g_count[b];
    if ((int)(blockIdx.x * blockDim.x) >= cnt) return;
    int i = blockIdx.x * blockDim.x + threadIdx.x;
    const unsigned long long* cand = g_cand + b * CAP;
    unsigned long long mykey = (i < cnt) ? cand[i] : 0ull;
    int rank = 0;
    __shared__ unsigned long long sk[256];
    for (int t = 0; t < cnt; t += 256) {
        int j = t + threadIdx.x;
        sk[threadIdx.x] = (j < cnt) ? cand[j] : 0ull;
        __syncthreads();
        int lim = min(256, cnt - t);
        if (i < cnt) {
            int u = 0;
            for (; u + 4 <= lim; u += 4) {
                rank += (sk[u]   > mykey) ? 1 : 0;
                rank += (sk[u+1] > mykey) ? 1 : 0;
                rank += (sk[u+2] > mykey) ? 1 : 0;
                rank += (sk[u+3] > mykey) ? 1 : 0;
            }
            for (; u < lim; ++u) rank += (sk[u] > mykey) ? 1 : 0;
        }
        __syncthreads();
    }
    if (i < cnt && rank < TOPK) {
        int flatidx = (int)(0xFFFFFFFFu - (unsigned)(mykey & 0xFFFFFFFFull));
        g_selidx[b * TOPK + rank] = flatidx;
    }
}

__device__ __forceinline__ float bilin1(const float* base, float x, float y) {
    float x0f = floorf(x), y0f = floorf(y);
    float wx = x - x0f, wy = y - y0f;
    int x0 = min(max((int)x0f, 0), WW - 1);
    int x1 = min(max((int)x0f + 1, 0), WW - 1);
    int y0 = min(max((int)y0f, 0), HH - 1);
    int y1 = min(max((int)y0f + 1, 0), HH - 1);
    float v00 = base[y0 * WW + x0], v01 = base[y0 * WW + x1];
    float v10 = base[y1 * WW + x0], v11 = base[y1 * WW + x1];
    return v00 * (1.f - wx) * (1.f - wy) + v01 * wx * (1.f - wy)
         + v10 * (1.f - wx) * wy + v11 * wx * wy;
}

// per-keypoint: 5x5 softmax refinement -> kxy, disp, kptscores
__global__ __launch_bounds__(128) void refine_k(const float* __restrict__ scores,
                                                float* __restrict__ out) {
    int t = blockIdx.x * blockDim.x + threadIdx.x;
    if (t >= NKP) return;
    int b = t >> 11;
    int idx = g_selidx[t];
    int ky = idx >> 9, kx = idx & 511;
    const float* sb = scores + b * HWSZ;

    float patch[25];
    float maxv = -INFINITY;
#pragma unroll
    for (int p = 0; p < 25; ++p) {
        int dy = p / 5 - 2, dx = p % 5 - 2;
        int y = ky + dy, x = kx + dx;
        float v = (y >= 0 && y < HH && x >= 0 && x < WW) ? sb[y * WW + x] : 0.0f;
        patch[p] = v;
        maxv = fmaxf(maxv, v);
    }
    float ex[25];
    float ssum = 0.f, sx = 0.f, sy = 0.f;
#pragma unroll
    for (int p = 0; p < 25; ++p) {
        float e = expf((patch[p] - maxv) * 10.0f);
        ex[p] = e;
        ssum += e;
        sx += e * (float)(p % 5 - 2);
        sy += e * (float)(p / 5 - 2);
    }
    float rx = sx / ssum, ry = sy / ssum;
    float disp = 0.f;
#pragma unroll
    for (int p = 0; p < 25; ++p) {
        float ddx = ((float)(p % 5 - 2) - rx) * 0.5f;
        float ddy = ((float)(p / 5 - 2) - ry) * 0.5f;
        disp += ex[p] * (ddx * ddx + ddy * ddy);
    }
    disp /= ssum;

    float kxf = ((float)kx + rx) / 511.f * 2.f - 1.f;
    float kyf = ((float)ky + ry) / 511.f * 2.f - 1.f;
    out[KXY_OFF + t * 2 + 0] = kxf;
    out[KXY_OFF + t * 2 + 1] = kyf;
    out[DISP_OFF + t] = disp;

    float xs = (kxf + 1.f) * 0.5f * (WW - 1);
    float ys = (kyf + 1.f) * 0.5f * (HH - 1);
    out[SC_OFF + t] = bilin1(sb, xs, ys);
}

// per-keypoint block of 128 threads: bilinear desc + L2 normalize
__global__ __launch_bounds__(128) void desc_k(const float* __restrict__ dmap,
                                              float* __restrict__ out) {
    int t = blockIdx.x;      // keypoint
    int c = threadIdx.x;     // channel
    int b = t >> 11;
    float kxf = out[KXY_OFF + t * 2 + 0];
    float kyf = out[KXY_OFF + t * 2 + 1];
    float x = (kxf + 1.f) * 0.5f * (WW - 1);
    float y = (kyf + 1.f) * 0.5f * (HH - 1);
    float x0f = floorf(x), y0f = floorf(y);
    float wx = x - x0f, wy = y - y0f;
    int x0 = min(max((int)x0f, 0), WW - 1);
    int x1 = min(max((int)x0f + 1, 0), WW - 1);
    int y0 = min(max((int)y0f, 0), HH - 1);
    int y1 = min(max((int)y0f + 1, 0), HH - 1);
    const float* base = dmap + ((size_t)b * 128 + c) * HWSZ;
    float v00 = base[y0 * WW + x0], v01 = base[y0 * WW + x1];
    float v10 = base[y1 * WW + x0], v11 = base[y1 * WW + x1];
    float v = v00 * (1.f - wx) * (1.f - wy) + v01 * wx * (1.f - wy)
            + v10 * (1.f - wx) * wy + v11 * wx * wy;

    // block L2-norm: warp shuffle + cross-warp smem
    float sq = v * v;
#pragma unroll
    for (int o = 16; o > 0; o >>= 1) sq += __shfl_xor_sync(0xFFFFFFFFu, sq, o);
    __shared__ float wsum[4];
    int wid = c >> 5;
    if ((c & 31) == 0) wsum[wid] = sq;
    __syncthreads();
    float tot = wsum[0] + wsum[1] + wsum[2] + wsum[3];
    float nrm = fmaxf(sqrtf(tot), 1e-12f);
    out[DESC_OFF + (size_t)t * 128 + c] = v / nrm;
}

extern "C" void kernel_launch(void* const* d_in, const int* in_sizes, int n_in,
                              void* d_out, int out_size) {
    // Identify inputs by element count (robust to metadata order)
    const float* scores;
    const float* dmap;
    if (in_sizes[0] == NPIX) {
        scores = (const float*)d_in[0];
        dmap   = (const float*)d_in[1];
    } else {
        scores = (const float*)d_in[1];
        dmap   = (const float*)d_in[0];
    }
    float* out = (float*)d_out;

    dim3 pg(WW / TX, HH / TY, BB);   // 8 x 32 x 2

    reset_k<<<1, 32>>>();

    pool_k<0,0><<<pg, 256>>>(scores);        // mm = (s == pool(s))
    // iteration 1
    pool_k<1,1><<<pg, 256>>>(scores);        // sm/ss from pool(mm)
    pool_k<2,2><<<pg, 256>>>(scores);        // mm |= (ss == pool(ss)) & ~sm
    // iteration 2 (+ fused candidate compaction)
    pool_k<1,1><<<pg, 256>>>(scores);
    pool_k<2,3><<<pg, 256>>>(scores);

    dim3 rgrid(CAP / 256, BB);
    rank_k<<<rgrid, 256>>>();

    refine_k<<<(NKP + 127) / 128, 128>>>(scores, out);
    desc_k<<<NKP, 128>>>(dmap, out);
}

// round 5
// speedup vs baseline: 1.2038x; 1.0500x over previous
#include <cuda_runtime.h>
#include <math.h>

#define HH 512
#define WW 512
#define BB 2
#define HWSZ (HH*WW)
#define NPIX (BB*HWSZ)
#define TOPK 2048
#define CAP 262144
#define NKP (BB*TOPK)

#define KXY_OFF  0
#define DESC_OFF (BB*TOPK*2)
#define SC_OFF   (DESC_OFF + BB*TOPK*128)
#define DISP_OFF (SC_OFF + BB*TOPK)

#define CTX 64
#define CTY 32
#define HAL 15
#define BW  96          // buffer col stride (94 used)
#define BHT 62          // buffer rows = CTY + 2*HAL
#define NBUF (BHT*BW)   // 5952 floats

__device__ unsigned long long g_cand[BB*CAP];
__device__ int g_count[BB];
__device__ int g_selidx[NKP];

__global__ void reset_k() {
    if (threadIdx.x < BB) g_count[threadIdx.x] = 0;
}

// Fully-fused split-half NMS (5 pools + mask logic + compaction) in one kernel.
__global__ __launch_bounds__(512) void nms_k(const float* __restrict__ scores) {
    extern __shared__ float sh[];
    float* S  = sh;
    float* MM = sh + NBUF;
    float* SS = sh + 2*NBUF;
    float* TP = sh + 3*NBUF;

    int tid = threadIdx.x;
    int b   = blockIdx.z;
    int gx0 = blockIdx.x * CTX - HAL;
    int gy0 = blockIdx.y * CTY - HAL;
    int hlo = ((int)(blockIdx.y * CTY) < 256) ? 0 : 256;
    int hhi = hlo + 255;
    const float* sb = scores + b * HWSZ;

    // load scores tile + halo; outside image / other half -> -inf
    for (int idx = tid; idx < NBUF; idx += 512) {
        int br = idx / BW, bc = idx % BW;
        int gy = gy0 + br, gx = gx0 + bc;
        float v = -INFINITY;
        if (bc < 94 && gy >= hlo && gy <= hhi && gx >= 0 && gx < WW)
            v = sb[gy * WW + gx];
        S[idx] = v;
    }
    __syncthreads();

#define VPASS(SRC)                                                        \
    for (int idx = tid; idx < 56*BW; idx += 512) {                        \
        int o = (3 + idx / BW) * BW + (idx % BW);                         \
        float m =        SRC[o - 3*BW];                                   \
        m = fmaxf(m, SRC[o - 2*BW]); m = fmaxf(m, SRC[o - BW]);           \
        m = fmaxf(m, SRC[o]);        m = fmaxf(m, SRC[o + BW]);           \
        m = fmaxf(m, SRC[o + 2*BW]); m = fmaxf(m, SRC[o + 3*BW]);         \
        TP[o] = m;                                                        \
    }                                                                     \
    __syncthreads();

#define HMAX(o, m)                                                        \
    float m =        TP[(o) - 3];                                         \
    m = fmaxf(m, TP[(o) - 2]); m = fmaxf(m, TP[(o) - 1]);                 \
    m = fmaxf(m, TP[(o)]);     m = fmaxf(m, TP[(o) + 1]);                 \
    m = fmaxf(m, TP[(o) + 2]); m = fmaxf(m, TP[(o) + 3]);

    // stage 1: mm = (s == pool(s))
    VPASS(S)
    for (int idx = tid; idx < 56*88; idx += 512) {
        int br = 3 + idx / 88, bc = 3 + idx % 88;
        int o = br * BW + bc;
        HMAX(o, m)
        int gy = gy0 + br, gx = gx0 + bc;
        bool valid = gy >= hlo && gy <= hhi && gx >= 0 && gx < WW;
        MM[o] = valid ? ((S[o] == m) ? 1.0f : 0.0f) : -INFINITY;
    }
    __syncthreads();

    // two recovery iterations; second fuses compaction (core only)
    for (int it = 0; it < 2; ++it) {
        // pool(mm) -> sm ; ss = sm ? -1 : s   (-1 sentinel == suppressed)
        VPASS(MM)
        for (int idx = tid; idx < 56*88; idx += 512) {
            int br = 3 + idx / 88, bc = 3 + idx % 88;
            int o = br * BW + bc;
            HMAX(o, m)
            int gy = gy0 + br, gx = gx0 + bc;
            bool valid = gy >= hlo && gy <= hhi && gx >= 0 && gx < WW;
            SS[o] = valid ? ((m > 0.0f) ? -1.0f : S[o]) : -INFINITY;
        }
        __syncthreads();

        VPASS(SS)
        if (it == 0) {
            // mm |= (ss unsuppressed && ss == pool(ss))
            for (int idx = tid; idx < 56*88; idx += 512) {
                int br = 3 + idx / 88, bc = 3 + idx % 88;
                int o = br * BW + bc;
                HMAX(o, m)
                float ssv = SS[o];
                if (MM[o] == 0.0f && ssv >= 0.0f && ssv == m) MM[o] = 1.0f;
            }
            __syncthreads();
        } else {
            // final update + border + candidate push, core region only
            for (int idx = tid; idx < CTY*CTX; idx += 512) {
                int br = HAL + idx / CTX, bc = HAL + idx % CTX;
                int o = br * BW + bc;
                HMAX(o, m)
                float ssv = SS[o];
                float mmv = MM[o];
                if (mmv == 0.0f && ssv >= 0.0f && ssv == m) mmv = 1.0f;
                int gy = gy0 + br, gx = gx0 + bc;
                int rem = gy * WW + gx;
                bool border = (gy >= 3) && (gy < 510) && (gx >= 3) && (gx < 510);
                float nms = (mmv > 0.0f && border) ? S[o] : 0.0f;
                if (nms > 0.0f || rem < TOPK) {
                    int pos = atomicAdd(&g_count[b], 1);
                    if (pos < CAP) {
                        unsigned long long key =
                            ((unsigned long long)__float_as_uint(nms) << 32) |
                            (unsigned long long)(0xFFFFFFFFu - (unsigned)rem);
                        g_cand[b * CAP + pos] = key;
                    }
                }
            }
        }
    }
}

// exact top-k by rank counting (unique keys -> exact (val desc, idx asc) order)
__global__ __launch_bounds__(256) void rank_k() {
    int b = blockIdx.y;
    int cnt = g_count[b];
    if ((int)(blockIdx.x * blockDim.x) >= cnt) return;
    int i = blockIdx.x * blockDim.x + threadIdx.x;
    const unsigned long long* cand = g_cand + b * CAP;
    unsigned long long mykey = (i < cnt) ? cand[i] : 0ull;
    int rank = 0;
    __shared__ unsigned long long sk[256];
    for (int t = 0; t < cnt; t += 256) {
        int j = t + threadIdx.x;
        sk[threadIdx.x] = (j < cnt) ? cand[j] : 0ull;
        __syncthreads();
        int lim = min(256, cnt - t);
        if (i < cnt) {
            int u = 0;
            for (; u + 4 <= lim; u += 4) {
                rank += (sk[u]   > mykey) ? 1 : 0;
                rank += (sk[u+1] > mykey) ? 1 : 0;
                rank += (sk[u+2] > mykey) ? 1 : 0;
                rank += (sk[u+3] > mykey) ? 1 : 0;
            }
            for (; u < lim; ++u) rank += (sk[u] > mykey) ? 1 : 0;
        }
        __syncthreads();
    }
    if (i < cnt && rank < TOPK) {
        int flatidx = (int)(0xFFFFFFFFu - (unsigned)(mykey & 0xFFFFFFFFull));
        g_selidx[b * TOPK + rank] = flatidx;
    }
}

__device__ __forceinline__ float bilin1(const float* base, float x, float y) {
    float x0f = floorf(x), y0f = floorf(y);
    float wx = x - x0f, wy = y - y0f;
    int x0 = min(max((int)x0f, 0), WW - 1);
    int x1 = min(max((int)x0f + 1, 0), WW - 1);
    int y0 = min(max((int)y0f, 0), HH - 1);
    int y1 = min(max((int)y0f + 1, 0), HH - 1);
    float v00 = base[y0 * WW + x0], v01 = base[y0 * WW + x1];
    float v10 = base[y1 * WW + x0], v11 = base[y1 * WW + x1];
    return v00 * (1.f - wx) * (1.f - wy) + v01 * wx * (1.f - wy)
         + v10 * (1.f - wx) * wy + v11 * wx * wy;
}

__global__ __launch_bounds__(128) void refine_k(const float* __restrict__ scores,
                                                float* __restrict__ out) {
    int t = blockIdx.x * blockDim.x + threadIdx.x;
    if (t >= NKP) return;
    int b = t >> 11;
    int idx = g_selidx[t];
    int ky = idx >> 9, kx = idx & 511;
    const float* sb = scores + b * HWSZ;

    float patch[25];
    float maxv = -INFINITY;
#pragma unroll
    for (int p = 0; p < 25; ++p) {
        int dy = p / 5 - 2, dx = p % 5 - 2;
        int y = ky + dy, x = kx + dx;
        float v = (y >= 0 && y < HH && x >= 0 && x < WW) ? sb[y * WW + x] : 0.0f;
        patch[p] = v;
        maxv = fmaxf(maxv, v);
    }
    float ex[25];
    float ssum = 0.f, sx = 0.f, sy = 0.f;
#pragma unroll
    for (int p = 0; p < 25; ++p) {
        float e = expf((patch[p] - maxv) * 10.0f);
        ex[p] = e;
        ssum += e;
        sx += e * (float)(p % 5 - 2);
        sy += e * (float)(p / 5 - 2);
    }
    float rx = sx / ssum, ry = sy / ssum;
    float disp = 0.f;
#pragma unroll
    for (int p = 0; p < 25; ++p) {
        float ddx = ((float)(p % 5 - 2) - rx) * 0.5f;
        float ddy = ((float)(p / 5 - 2) - ry) * 0.5f;
        disp += ex[p] * (ddx * ddx + ddy * ddy);
    }
    disp /= ssum;

    float kxf = ((float)kx + rx) / 511.f * 2.f - 1.f;
    float kyf = ((float)ky + ry) / 511.f * 2.f - 1.f;
    out[KXY_OFF + t * 2 + 0] = kxf;
    out[KXY_OFF + t * 2 + 1] = kyf;
    out[DISP_OFF + t] = disp;

    float xs = (kxf + 1.f) * 0.5f * (WW - 1);
    float ys = (kyf + 1.f) * 0.5f * (HH - 1);
    out[SC_OFF + t] = bilin1(sb, xs, ys);
}

__global__ __launch_bounds__(128) void desc_k(const float* __restrict__ dmap,
                                              float* __restrict__ out) {
    int t = blockIdx.x;
    int c = threadIdx.x;
    int b = t >> 11;
    float kxf = out[KXY_OFF + t * 2 + 0];
    float kyf = out[KXY_OFF + t * 2 + 1];
    float x = (kxf + 1.f) * 0.5f * (WW - 1);
    float y = (kyf + 1.f) * 0.5f * (HH - 1);
    float x0f = floorf(x), y0f = floorf(y);
    float wx = x - x0f, wy = y - y0f;
    int x0 = min(max((int)x0f, 0), WW - 1);
    int x1 = min(max((int)x0f + 1, 0), WW - 1);
    int y0 = min(max((int)y0f, 0), HH - 1);
    int y1 = min(max((int)y0f + 1, 0), HH - 1);
    const float* base = dmap + ((size_t)b * 128 + c) * HWSZ;
    float v00 = base[y0 * WW + x0], v01 = base[y0 * WW + x1];
    float v10 = base[y1 * WW + x0], v11 = base[y1 * WW + x1];
    float v = v00 * (1.f - wx) * (1.f - wy) + v01 * wx * (1.f - wy)
            + v10 * (1.f - wx) * wy + v11 * wx * wy;

    float sq = v * v;
#pragma unroll
    for (int o = 16; o > 0; o >>= 1) sq += __shfl_xor_sync(0xFFFFFFFFu, sq, o);
    __shared__ float wsum[4];
    int wid = c >> 5;
    if ((c & 31) == 0) wsum[wid] = sq;
    __syncthreads();
    float tot = wsum[0] + wsum[1] + wsum[2] + wsum[3];
    float nrm = fmaxf(sqrtf(tot), 1e-12f);
    out[DESC_OFF + (size_t)t * 128 + c] = v / nrm;
}

extern "C" void kernel_launch(void* const* d_in, const int* in_sizes, int n_in,
                              void* d_out, int out_size) {
    const float* scores;
    const float* dmap;
    if (in_sizes[0] == NPIX) {
        scores = (const float*)d_in[0];
        dmap   = (const float*)d_in[1];
    } else {
        scores = (const float*)d_in[1];
        dmap   = (const float*)d_in[0];
    }
    float* out = (float*)d_out;

    static bool attr_done = false;
    if (!attr_done) {
        cudaFuncSetAttribute(nms_k, cudaFuncAttributeMaxDynamicSharedMemorySize,
                             4 * NBUF * (int)sizeof(float));
        attr_done = true;
    }

    reset_k<<<1, 32>>>();

    dim3 ng(WW / CTX, HH / CTY, BB);   // 8 x 16 x 2
    nms_k<<<ng, 512, 4 * NBUF * sizeof(float)>>>(scores);

    dim3 rgrid(CAP / 256, BB);
    rank_k<<<rgrid, 256>>>();

    refine_k<<<(NKP + 127) / 128, 128>>>(scores, out);
    desc_k<<<NKP, 128>>>(dmap, out);
}

// round 6
// speedup vs baseline: 3.4190x; 2.8403x over previous
#include <cuda_runtime.h>
#include <math.h>

#define HH 512
#define WW 512
#define BB 2
#define HWSZ (HH*WW)
#define NPIX (BB*HWSZ)
#define TOPK 2048
#define CAP 262144
#define NKP (BB*TOPK)
#define NBINS 4096

#define KXY_OFF  0
#define DESC_OFF (BB*TOPK*2)
#define SC_OFF   (DESC_OFF + BB*TOPK*128)
#define DISP_OFF (SC_OFF + BB*TOPK)

#define CTX 64
#define CTY 32
#define HAL 15
#define BW  96
#define BHT 62
#define NBUF (BHT*BW)

__device__ unsigned long long g_cand[BB*CAP];
__device__ unsigned long long g_surv[BB*CAP];
__device__ int g_count[BB];
__device__ int g_scount[BB];
__device__ int g_T[BB];
__device__ int g_hist[BB*NBINS];
__device__ int g_selidx[NKP];

__global__ void reset_k() {
    int i = blockIdx.x * 1024 + threadIdx.x;
    if (i < BB*NBINS) g_hist[i] = 0;
    if (i < BB) { g_count[i] = 0; g_scount[i] = 0; }
}

// Fully-fused split-half NMS (5 pools + mask logic + compaction + histogram).
__global__ __launch_bounds__(512) void nms_k(const float* __restrict__ scores) {
    extern __shared__ float sh[];
    float* S  = sh;
    float* MM = sh + NBUF;
    float* SS = sh + 2*NBUF;
    float* TP = sh + 3*NBUF;

    int tid = threadIdx.x;
    int b   = blockIdx.z;
    int gx0 = blockIdx.x * CTX - HAL;
    int gy0 = blockIdx.y * CTY - HAL;
    int hlo = ((int)(blockIdx.y * CTY) < 256) ? 0 : 256;
    int hhi = hlo + 255;
    const float* sb = scores + b * HWSZ;

    for (int idx = tid; idx < NBUF; idx += 512) {
        int br = idx / BW, bc = idx % BW;
        int gy = gy0 + br, gx = gx0 + bc;
        float v = -INFINITY;
        if (bc < 94 && gy >= hlo && gy <= hhi && gx >= 0 && gx < WW)
            v = sb[gy * WW + gx];
        S[idx] = v;
    }
    __syncthreads();

// vertical 7-max pass for output halo H over SRC -> TP
#define VPASS(SRC, H)                                                          \
    {                                                                          \
        const int R = CTY + 2*(H), C = CTX + 2*(H) + 6;                        \
        for (int idx = tid; idx < R*C; idx += 512) {                           \
            int o = ((HAL-(H)) + idx / C) * BW + ((HAL-(H)-3) + idx % C);      \
            float m =        SRC[o - 3*BW];                                    \
            m = fmaxf(m, SRC[o - 2*BW]); m = fmaxf(m, SRC[o - BW]);            \
            m = fmaxf(m, SRC[o]);        m = fmaxf(m, SRC[o + BW]);            \
            m = fmaxf(m, SRC[o + 2*BW]); m = fmaxf(m, SRC[o + 3*BW]);          \
            TP[o] = m;                                                         \
        }                                                                      \
        __syncthreads();                                                       \
    }

#define HMAX(o, m)                                                             \
    float m =        TP[(o) - 3];                                              \
    m = fmaxf(m, TP[(o) - 2]); m = fmaxf(m, TP[(o) - 1]);                      \
    m = fmaxf(m, TP[(o)]);     m = fmaxf(m, TP[(o) + 1]);                      \
    m = fmaxf(m, TP[(o) + 2]); m = fmaxf(m, TP[(o) + 3]);

    // stage 1 (out halo 12): mm = (s == pool(s)); invalid -> -inf
    VPASS(S, 12)
    {
        const int R = CTY + 24, C = CTX + 24;
        for (int idx = tid; idx < R*C; idx += 512) {
            int br = 3 + idx / C, bc = 3 + idx % C;
            int o = br * BW + bc;
            HMAX(o, m)
            int gy = gy0 + br, gx = gx0 + bc;
            bool valid = gy >= hlo && gy <= hhi && gx >= 0 && gx < WW;
            MM[o] = valid ? ((S[o] == m) ? 1.0f : 0.0f) : -INFINITY;
        }
        __syncthreads();
    }

    // iteration 1: ss(h9) = supp? -1 : s ; mm(h6) |= (ss>=0 && ss==pool(ss))
    VPASS(MM, 9)
    {
        const int R = CTY + 18, C = CTX + 18;
        for (int idx = tid; idx < R*C; idx += 512) {
            int br = 6 + idx / C, bc = 6 + idx % C;
            int o = br * BW + bc;
            HMAX(o, m)
            int gy = gy0 + br, gx = gx0 + bc;
            bool valid = gy >= hlo && gy <= hhi && gx >= 0 && gx < WW;
            SS[o] = valid ? ((m > 0.0f) ? -1.0f : S[o]) : -INFINITY;
        }
        __syncthreads();
    }
    VPASS(SS, 6)
    {
        const int R = CTY + 12, C = CTX + 12;
        for (int idx = tid; idx < R*C; idx += 512) {
            int br = 9 + idx / C, bc = 9 + idx % C;
            int o = br * BW + bc;
            HMAX(o, m)
            float ssv = SS[o];
            if (MM[o] == 0.0f && ssv >= 0.0f && ssv == m) MM[o] = 1.0f;
        }
        __syncthreads();
    }

    // iteration 2: ss(h3); final update + compaction at core (h0)
    VPASS(MM, 3)
    {
        const int R = CTY + 6, C = CTX + 6;
        for (int idx = tid; idx < R*C; idx += 512) {
            int br = 12 + idx / C, bc = 12 + idx % C;
            int o = br * BW + bc;
            HMAX(o, m)
            int gy = gy0 + br, gx = gx0 + bc;
            bool valid = gy >= hlo && gy <= hhi && gx >= 0 && gx < WW;
            SS[o] = valid ? ((m > 0.0f) ? -1.0f : S[o]) : -INFINITY;
        }
        __syncthreads();
    }
    VPASS(SS, 0)
    {
        for (int idx = tid; idx < CTY*CTX; idx += 512) {
            int br = HAL + idx / CTX, bc = HAL + idx % CTX;
            int o = br * BW + bc;
            HMAX(o, m)
            float ssv = SS[o];
            float mmv = MM[o];
            if (mmv == 0.0f && ssv >= 0.0f && ssv == m) mmv = 1.0f;
            int gy = gy0 + br, gx = gx0 + bc;
            int rem = gy * WW + gx;
            bool border = (gy >= 3) && (gy < 510) && (gx >= 3) && (gx < 510);
            float nms = (mmv > 0.0f && border) ? S[o] : 0.0f;
            if (nms > 0.0f || rem < TOPK) {
                int pos = atomicAdd(&g_count[b], 1);
                if (pos < CAP) {
                    unsigned long long key =
                        ((unsigned long long)__float_as_uint(nms) << 32) |
                        (unsigned long long)(0xFFFFFFFFu - (unsigned)rem);
                    g_cand[b * CAP + pos] = key;
                    int bin = min(NBINS-1, max(0, (int)(nms * (float)NBINS)));
                    atomicAdd(&g_hist[b * NBINS + bin], 1);
                }
            }
        }
    }
}

// per-batch: find smallest bin T with suffix-count >= TOPK
__global__ __launch_bounds__(1024) void thresh_k() {
    int b = blockIdx.x;
    int t = threadIdx.x;
    __shared__ int gs[1024];
    int base = NBINS - 1 - 4*t;
    int c0 = g_hist[b*NBINS + base];
    int c1 = g_hist[b*NBINS + base-1];
    int c2 = g_hist[b*NBINS + base-2];
    int c3 = g_hist[b*NBINS + base-3];
    int s = c0 + c1 + c2 + c3;
    gs[t] = s;
    __syncthreads();
    for (int off = 1; off < 1024; off <<= 1) {
        int v = (t >= off) ? gs[t-off] : 0;
        __syncthreads();
        gs[t] += v;
        __syncthreads();
    }
    int total = gs[1023];
    int excl = gs[t] - s;
    if (excl < TOPK && excl + s >= TOPK) {
        int T = base - 3;
        int cum = excl + c0;
        if (cum >= TOPK) T = base;
        else { cum += c1; if (cum >= TOPK) T = base-1;
               else { cum += c2; if (cum >= TOPK) T = base-2; } }
        g_T[b] = T;
    }
    if (t == 0 && total < TOPK) g_T[b] = 0;
}

// keep only candidates with bin >= T
__global__ __launch_bounds__(256) void compact2_k() {
    int b = blockIdx.y;
    int cnt = g_count[b];
    if ((int)(blockIdx.x * blockDim.x) >= cnt) return;
    int i = blockIdx.x * blockDim.x + threadIdx.x;
    if (i >= cnt) return;
    int T = g_T[b];
    unsigned long long key = g_cand[b*CAP + i];
    float v = __uint_as_float((unsigned)(key >> 32));
    int bin = min(NBINS-1, max(0, (int)(v * (float)NBINS)));
    if (bin >= T) {
        int p = atomicAdd(&g_scount[b], 1);
        g_surv[b*CAP + p] = key;
    }
}

// exact rank among survivors (== global rank since bin monotone in value)
__global__ __launch_bounds__(256) void rank2_k() {
    int b = blockIdx.y;
    int m = g_scount[b];
    if ((int)(blockIdx.x * blockDim.x) >= m) return;
    int i = blockIdx.x * blockDim.x + threadIdx.x;
    const unsigned long long* sv = g_surv + b*CAP;
    unsigned long long mykey = (i < m) ? sv[i] : 0ull;
    int rank = 0;
    __shared__ unsigned long long sk[256];
    for (int t = 0; t < m; t += 256) {
        int j = t + threadIdx.x;
        sk[threadIdx.x] = (j < m) ? sv[j] : 0ull;
        __syncthreads();
        int lim = min(256, m - t);
        if (i < m) {
            int u = 0;
            for (; u + 4 <= lim; u += 4) {
                rank += (sk[u]   > mykey) ? 1 : 0;
                rank += (sk[u+1] > mykey) ? 1 : 0;
                rank += (sk[u+2] > mykey) ? 1 : 0;
                rank += (sk[u+3] > mykey) ? 1 : 0;
            }
            for (; u < lim; ++u) rank += (sk[u] > mykey) ? 1 : 0;
        }
        __syncthreads();
    }
    if (i < m && rank < TOPK) {
        int flatidx = (int)(0xFFFFFFFFu - (unsigned)(mykey & 0xFFFFFFFFull));
        g_selidx[b * TOPK + rank] = flatidx;
    }
}

__device__ __forceinline__ float bilin1(const float* base, float x, float y) {
    float x0f = floorf(x), y0f = floorf(y);
    float wx = x - x0f, wy = y - y0f;
    int x0 = min(max((int)x0f, 0), WW - 1);
    int x1 = min(max((int)x0f + 1, 0), WW - 1);
    int y0 = min(max((int)y0f, 0), HH - 1);
    int y1 = min(max((int)y0f + 1, 0), HH - 1);
    float v00 = base[y0 * WW + x0], v01 = base[y0 * WW + x1];
    float v10 = base[y1 * WW + x0], v11 = base[y1 * WW + x1];
    return v00 * (1.f - wx) * (1.f - wy) + v01 * wx * (1.f - wy)
         + v10 * (1.f - wx) * wy + v11 * wx * wy;
}

// fused: warp0 does 5x5 softmax refine; all 128 threads do descriptor sample+norm
__global__ __launch_bounds__(128) void refine_desc_k(const float* __restrict__ scores,
                                                     const float* __restrict__ dmap,
                                                     float* __restrict__ out) {
    int t = blockIdx.x;            // keypoint
    int c = threadIdx.x;           // channel / lane role
    int b = t >> 11;
    int w = c >> 5, lane = c & 31;
    __shared__ float sxy[2];

    if (w == 0) {
        int idx = g_selidx[t];
        int ky = idx >> 9, kx = idx & 511;
        const float* sb = scores + b * HWSZ;
        int p = lane;
        float dxf = 0.f, dyf = 0.f, v = 0.f;
        if (p < 25) {
            int dy = p / 5 - 2, dx = p % 5 - 2;
            dxf = (float)dx; dyf = (float)dy;
            int y = ky + dy, x = kx + dx;
            v = (y >= 0 && y < HH && x >= 0 && x < WW) ? sb[y * WW + x] : 0.0f;
        }
        float pv = (p < 25) ? v : -INFINITY;
#pragma unroll
        for (int o = 16; o > 0; o >>= 1) pv = fmaxf(pv, __shfl_xor_sync(0xFFFFFFFFu, pv, o));
        float e = (p < 25) ? expf((v - pv) * 10.0f) : 0.0f;
        float se = e, sxv = e * dxf, syv = e * dyf;
#pragma unroll
        for (int o = 16; o > 0; o >>= 1) {
            se  += __shfl_xor_sync(0xFFFFFFFFu, se, o);
            sxv += __shfl_xor_sync(0xFFFFFFFFu, sxv, o);
            syv += __shfl_xor_sync(0xFFFFFFFFu, syv, o);
        }
        float rx = sxv / se, ry = syv / se;
        float ddx = (dxf - rx) * 0.5f, ddy = (dyf - ry) * 0.5f;
        float dc = e * (ddx * ddx + ddy * ddy);
#pragma unroll
        for (int o = 16; o > 0; o >>= 1) dc += __shfl_xor_sync(0xFFFFFFFFu, dc, o);

        if (lane == 0) {
            float kxf = ((float)kx + rx) / 511.f * 2.f - 1.f;
            float kyf = ((float)ky + ry) / 511.f * 2.f - 1.f;
            out[KXY_OFF + t * 2 + 0] = kxf;
            out[KXY_OFF + t * 2 + 1] = kyf;
            out[DISP_OFF + t] = dc / se;
            float xs = (kxf + 1.f) * 0.5f * (WW - 1);
            float ys = (kyf + 1.f) * 0.5f * (HH - 1);
            out[SC_OFF + t] = bilin1(sb, xs, ys);
            sxy[0] = xs; sxy[1] = ys;
        }
    }
    __syncthreads();

    float x = sxy[0], y = sxy[1];
    float x0f = floorf(x), y0f = floorf(y);
    float wx = x - x0f, wy = y - y0f;
    int x0 = min(max((int)x0f, 0), WW - 1);
    int x1 = min(max((int)x0f + 1, 0), WW - 1);
    int y0 = min(max((int)y0f, 0), HH - 1);
    int y1 = min(max((int)y0f + 1, 0), HH - 1);
    const float* base = dmap + ((size_t)b * 128 + c) * HWSZ;
    float v00 = base[y0 * WW + x0], v01 = base[y0 * WW + x1];
    float v10 = base[y1 * WW + x0], v11 = base[y1 * WW + x1];
    float v = v00 * (1.f - wx) * (1.f - wy) + v01 * wx * (1.f - wy)
            + v10 * (1.f - wx) * wy + v11 * wx * wy;

    float sq = v * v;
#pragma unroll
    for (int o = 16; o > 0; o >>= 1) sq += __shfl_xor_sync(0xFFFFFFFFu, sq, o);
    __shared__ float wsum[4];
    if (lane == 0) wsum[w] = sq;
    __syncthreads();
    float tot = wsum[0] + wsum[1] + wsum[2] + wsum[3];
    float nrm = fmaxf(sqrtf(tot), 1e-12f);
    out[DESC_OFF + (size_t)t * 128 + c] = v / nrm;
}

extern "C" void kernel_launch(void* const* d_in, const int* in_sizes, int n_in,
                              void* d_out, int out_size) {
    const float* scores;
    const float* dmap;
    if (in_sizes[0] == NPIX) {
        scores = (const float*)d_in[0];
        dmap   = (const float*)d_in[1];
    } else {
        scores = (const float*)d_in[1];
        dmap   = (const float*)d_in[0];
    }
    float* out = (float*)d_out;

    static bool attr_done = false;
    if (!attr_done) {
        cudaFuncSetAttribute(nms_k, cudaFuncAttributeMaxDynamicSharedMemorySize,
                             4 * NBUF * (int)sizeof(float));
        attr_done = true;
    }

    reset_k<<<8, 1024>>>();

    dim3 ng(WW / CTX, HH / CTY, BB);
    nms_k<<<ng, 512, 4 * NBUF * sizeof(float)>>>(scores);

    thresh_k<<<BB, 1024>>>();

    dim3 cg(CAP / 256, BB);
    compact2_k<<<cg, 256>>>();
    rank2_k<<<cg, 256>>>();

    refine_desc_k<<<NKP, 128>>>(scores, dmap, out);
}